// round 6
// baseline (speedup 1.0000x reference)
#include <cuda_runtime.h>
#include <math.h>

// NUFFT layer, analytic band-limited reformulation (round-1 header for math).
// Round-6: round-5 fused persistent kernel with the __ldg bug fixed — g_tab is
// written in-kernel (phase B), so reading it through the read-only path let the
// compiler hoist loads above the grid barrier (first-launch rel_err 0.716,
// ~sqrt(1/2) = half the field contribution zero). Plain loads now; spin asm
// gains a "memory" clobber.

#define NMODES 112          // modes >= 106 underflow to exactly 0 (as reference fp32)
#define NBATCH 8
#define NPART  1024
#define NMESHC 2001
#define GRIDB  148
#define TPB    448

__device__ float    g_part2[NBATCH][2 * NMODES][32];  // [b][A|B x mode][group]
__device__ float4   g_tab[NBATCH * NMODES];           // (A, B, V0, V1)
__device__ float    g_f[NBATCH][2][NMESHC];
__device__ unsigned g_ctr[3];                         // monotonic barrier counters

#define TWO_PI_F 6.2831853071795864769f

__device__ __forceinline__ float frac_mx(float m, float x)
{   // frac(m*x) in ~[-0.5,0.5]; exact split (m < 2^7, x fp32)
    float hi = m * x;
    float lo = fmaf(m, x, -hi);
    return (hi - rintf(hi)) + lo;
}

__device__ __forceinline__ void grid_barrier(int i)
{
    __syncthreads();
    if (threadIdx.x == 0) {
        __threadfence();
        unsigned v   = atomicAdd(&g_ctr[i], 1u);
        unsigned tgt = v - (v % GRIDB) + GRIDB;   // end of this replay's wave
        unsigned cur;
        do {
            asm volatile("ld.acquire.gpu.u32 %0, [%1];"
                         : "=r"(cur) : "l"(&g_ctr[i]) : "memory");
        } while ((int)(cur - tgt) < 0);
    }
    __syncthreads();
}

__global__ __launch_bounds__(TPB) void k_fused(
    const float* __restrict__ x,
    const float* __restrict__ sigma_var,
    const float* __restrict__ shift0,
    const float* __restrict__ shift1,
    const float* __restrict__ amp0,
    const float* __restrict__ amp1,
    float* __restrict__ out)
{
    const int bb   = blockIdx.x;
    const int tid  = threadIdx.x;
    const int w    = tid >> 5;
    const int lane = tid & 31;

    // ---------------- Phase A: per-mode cos/sin partial sums -------------
    // Blocks 0..127: (pg = bb&15, b = bb>>4); warp: chunk c = w%7, half h = w/7.
    // Lane = one particle. 31-shfl distributed reduction -> one value/thread.
    if (bb < 128) {
        const int pg = bb & 15;
        const int b  = bb >> 4;
        const int c  = w % 7;
        const int h  = w / 7;
        const float xv = x[b * NPART + pg * 64 + h * 32 + lane];

        float sw_, cw_;                               // step e^{2*pi*i*x}
        __sincosf(TWO_PI_F * (xv - rintf(xv)), &sw_, &cw_);
        float zr, zi;
        if (c == 0) { zr = 1.f; zi = 0.f; }
        else        { __sincosf(TWO_PI_F * frac_mx((float)(16 * c), xv), &zi, &zr); }

        float v[32];                                  // v[2j]=cos, v[2j+1]=sin
#pragma unroll
        for (int j = 0; j < 16; ++j) {
            v[2 * j]     = zr;
            v[2 * j + 1] = zi;
            float nzr = fmaf(zr, cw_, -zi * sw_);
            float nzi = fmaf(zi, cw_,  zr * sw_);
            zr = nzr; zi = nzi;
        }
#pragma unroll
        for (int s = 0; s < 5; ++s) {                 // recursive halving, 31 shfls
            const int  half = 16 >> s;
            const bool up   = (lane >> s) & 1;
#pragma unroll
            for (int k = 0; k < half; ++k) {
                float send = up ? v[k] : v[k + half];
                float recv = __shfl_xor_sync(0xffffffffu, send, 1 << s);
                v[k] = (up ? v[k + half] : v[k]) + recv;
            }
        }
        const int r = __brev(lane) >> 27;             // original accumulator idx
        const int m = 16 * c + (r >> 1);
        g_part2[b][(r & 1) * NMODES + m][pg * 2 + h] = v[0];
    }

    grid_barrier(0);

    // ---------------- Phase B: reduce partials + spectral multipliers ----
    // Blocks 0..63: b = bb>>3, 14-mode chunk = bb&7; warp w -> mode; lane = group.
    if (bb < 64) {
        const int b = bb >> 3;
        const int m = (bb & 7) * 14 + w;
        float a  = g_part2[b][m][lane];
        float bv = g_part2[b][NMODES + m][lane];
#pragma unroll
        for (int s = 1; s < 32; s <<= 1) {
            a  += __shfl_xor_sync(0xffffffffu, a,  s);
            bv += __shfl_xor_sync(0xffffffffu, bv, s);
        }
        if (lane == 0) {
            const double TWO_PI_D = 6.283185307179586476925286766559;
            const double taud  = 12.0 / ((TWO_PI_D * 2001.0) * (TWO_PI_D * 2001.0));
            const float TAUF     = (float)taud;
            const float SQPIOTAU = (float)sqrt(3.14159265358979323846 / taud);
            const float s_   = sigma_var[0];
            const float q0   = 25.f * shift0[0] * shift0[0];
            const float q1   = 25.f * shift1[0] * shift1[0];
            const float FOURPI = 12.566370614359172f;
            const float coef = TAUF - 0.5f * s_ * s_;
            float kk = TWO_PI_F * (float)m;
            float K2 = kk * kk;
            float e  = SQPIOTAU * __expf(coef * K2);  // 0 for m >= 106 (as ref)
            float fold = (m == 0) ? 1.f : 2.f;
            float V0 = fold * (-amp0[0]) * FOURPI / (K2 + q0) * e;
            float inv = 1.f / (K2 + q1);
            float V1 = fold * amp1[0] * FOURPI * inv * inv * e;
            g_tab[b * NMODES + m] = make_float4(a, bv, V0, V1);
        }
    }

    grid_barrier(1);

    // ---------------- Phase C: field at 8 x 2001 grid points -------------
    // slot = bb*112 + tid/4 (b = slot>>11, n = slot&2047); 4 threads/slot,
    // 28-mode rotation chain each, combined with 2 shfl_xor.
    {
        const int q    = tid & 3;
        const int slot = bb * 112 + (tid >> 2);
        const int bidx = (slot >> 11) & 7;
        const int n    = slot & 2047;
        const bool pv  = (slot < 16384) && (n < NMESHC);

        const float C_HI = (float)(1.0 / 2001.0);
        const float C_LO = (float)(1.0 / 2001.0 - (double)((float)(1.0 / 2001.0)));
        const float nf     = (float)n;
        const float phi_hi = nf * C_HI;
        const float phi_lo = fmaf(nf, C_HI, -phi_hi) + nf * C_LO;

        float sw_, cw_;                               // step e^{2*pi*i*phi}
        __sincosf(TWO_PI_F * ((phi_hi - rintf(phi_hi)) + phi_lo), &sw_, &cw_);

        float zr, zi;                                 // base at m0 = 28*q (exact)
        if (q == 0) { zr = 1.f; zi = 0.f; }
        else {
            float m0f = (float)(28 * q);
            float hi2 = m0f * phi_hi;
            float lo2 = fmaf(m0f, phi_hi, -hi2);
            float f   = (hi2 - rintf(hi2)) + (lo2 + m0f * phi_lo);
            __sincosf(TWO_PI_F * (f - rintf(f)), &zi, &zr);
        }

        float acc0 = 0.f, acc1 = 0.f;
        const float4* tab = &g_tab[bidx * NMODES + 28 * q];
#pragma unroll
        for (int j = 0; j < 28; ++j) {
            float4 t4 = tab[j];                       // PLAIN load: g_tab is
            float tt = fmaf(t4.x, zr, t4.y * zi);     // written in-kernel (no __ldg!)
            acc0 = fmaf(t4.z, tt, acc0);
            acc1 = fmaf(t4.w, tt, acc1);
            float nzr = fmaf(zr, cw_, -zi * sw_);
            float nzi = fmaf(zi, cw_,  zr * sw_);
            zr = nzr; zi = nzi;
        }
        acc0 += __shfl_xor_sync(0xffffffffu, acc0, 1);
        acc0 += __shfl_xor_sync(0xffffffffu, acc0, 2);
        acc1 += __shfl_xor_sync(0xffffffffu, acc1, 1);
        acc1 += __shfl_xor_sync(0xffffffffu, acc1, 2);
        if (q == 0 && pv) {
            g_f[bidx][0][n] = acc0;
            g_f[bidx][1][n] = acc1;
        }
    }

    grid_barrier(2);

    // ---------------- Phase D: resample at particle positions ------------
    {
        const int p = bb * 56 + tid;                  // 148*56 = 8288 >= 8192
        if (tid < 56 && p < NBATCH * NPART) {
            const int b = p >> 10;
            const float xv = x[p];

            const double TWO_PI_D = 6.283185307179586476925286766559;
            const float TAUF    = (float)(12.0 / ((TWO_PI_D * 2001.0) * (TWO_PI_D * 2001.0)));
            const float inv4tau = 1.f / (4.f * TAUF);
            const float C_HI = (float)(1.0 / 2001.0);
            const float C_LO = (float)(1.0 / 2001.0 - (double)((float)(1.0 / 2001.0)));

            const int m0 = __float2int_rn(xv * 2001.0f);
            float acc0 = 0.f, acc1 = 0.f;
#pragma unroll
            for (int j = -7; j <= 7; ++j) {
                int m = m0 + j;
                if (m < 0 || m > 2000) continue;
                float mf = (float)m;
                float hi = mf * C_HI;
                float X  = hi + (fmaf(mf, C_HI, -hi) + mf * C_LO);  // fp32(m/2001)
                float d  = xv - X;
                float wgt = __expf(-d * d * inv4tau);
                acc0 = fmaf(wgt, g_f[b][0][m], acc0);
                acc1 = fmaf(wgt, g_f[b][1][m], acc1);
            }
            const float invN = (float)(1.0 / 2001.0);
            out[2 * p]     = acc0 * invN;
            out[2 * p + 1] = acc1 * invN;
        }
    }
}

// ---------------------------------------------------------------------------
extern "C" void kernel_launch(void* const* d_in, const int* in_sizes, int n_in,
                              void* d_out, int out_size)
{
    (void)in_sizes; (void)n_in; (void)out_size;
    k_fused<<<GRIDB, TPB>>>((const float*)d_in[0], (const float*)d_in[1],
                            (const float*)d_in[2], (const float*)d_in[3],
                            (const float*)d_in[4], (const float*)d_in[5],
                            (float*)d_out);
}

// round 7
// speedup vs baseline: 1.1404x; 1.1404x over previous
#include <cuda_runtime.h>
#include <math.h>

// NUFFT layer, analytic band-limited reformulation (round-1 header for math).
// Round-7: fused persistent kernel, 2 barriers (was 3). Phase A accumulators
// shrunk to v[16] (8 modes/warp x 14 warps = 112) — round-6's v[32] spilled
// (regs=32 reported, L1 21.3%). Spectral reduction+multipliers are now done
// per-block into SMEM (kills barrier 1 and turns phase-C table reads into LDS).

#define NMODES 112          // modes >= 106 underflow to exactly 0 (as reference fp32)
#define NBATCH 8
#define NPART  1024
#define NMESHC 2001
#define GRIDB  148
#define TPB    448

__device__ float    g_part2[NBATCH][2 * NMODES][16];  // [b][A|B x mode][pgroup]
__device__ float    g_f[NBATCH][2][NMESHC];
__device__ unsigned g_ctr[2];                         // monotonic barrier counters

#define TWO_PI_F 6.2831853071795864769f

__device__ __forceinline__ float frac_mx(float m, float x)
{   // frac(m*x) in ~[-0.5,0.5]; exact Dekker split (m <= 104 < 2^7, x fp32)
    float hi = m * x;
    float lo = fmaf(m, x, -hi);
    return (hi - rintf(hi)) + lo;
}

__device__ __forceinline__ void grid_barrier(int i)
{
    __syncthreads();
    if (threadIdx.x == 0) {
        __threadfence();
        unsigned v   = atomicAdd(&g_ctr[i], 1u);
        unsigned tgt = v - (v % GRIDB) + GRIDB;   // end of this replay's wave
        unsigned cur;
        do {
            asm volatile("ld.acquire.gpu.u32 %0, [%1];"
                         : "=r"(cur) : "l"(&g_ctr[i]) : "memory");
        } while ((int)(cur - tgt) < 0);
    }
    __syncthreads();
}

__global__ __launch_bounds__(TPB, 1) void k_fused(
    const float* __restrict__ x,
    const float* __restrict__ sigma_var,
    const float* __restrict__ shift0,
    const float* __restrict__ shift1,
    const float* __restrict__ amp0,
    const float* __restrict__ amp1,
    float* __restrict__ out)
{
    const int bb   = blockIdx.x;
    const int tid  = threadIdx.x;
    const int w    = tid >> 5;
    const int lane = tid & 31;

    __shared__ float  rowsum[2 * NMODES];
    __shared__ float4 tab4[NMODES];

    // ---------------- Phase A: per-mode cos/sin partial sums -------------
    // Blocks 0..127: (pg = bb&15, b = bb>>4) own 64 particles. Warp w owns
    // modes 8w..8w+7 (v[16] accumulators, 2 particles per lane, pure FMA).
    if (bb < 128) {
        const int pg = bb & 15;
        const int b  = bb >> 4;

        float v[16];
#pragma unroll
        for (int k = 0; k < 16; ++k) v[k] = 0.f;

#pragma unroll
        for (int pp = 0; pp < 2; ++pp) {
            const float xv = x[b * NPART + pg * 64 + pp * 32 + lane];
            float sw_, cw_;                           // step e^{2*pi*i*x}
            __sincosf(TWO_PI_F * (xv - rintf(xv)), &sw_, &cw_);
            float zr, zi;
            if (w == 0) { zr = 1.f; zi = 0.f; }
            else        { __sincosf(TWO_PI_F * frac_mx((float)(8 * w), xv), &zi, &zr); }
#pragma unroll
            for (int j = 0; j < 8; ++j) {
                v[2 * j]     += zr;
                v[2 * j + 1] += zi;
                float nzr = fmaf(zr, cw_, -zi * sw_);
                float nzi = fmaf(zi, cw_,  zr * sw_);
                zr = nzr; zi = nzi;
            }
        }
        // 4-stage recursive halving (15 shfls) + final cross-half add.
#pragma unroll
        for (int s = 0; s < 4; ++s) {
            const int  half = 8 >> s;
            const bool up   = (lane >> s) & 1;
#pragma unroll
            for (int k = 0; k < half; ++k) {
                float send = up ? v[k] : v[k + half];
                float recv = __shfl_xor_sync(0xffffffffu, send, 1 << s);
                v[k] = (up ? v[k + half] : v[k]) + recv;
            }
        }
        v[0] += __shfl_xor_sync(0xffffffffu, v[0], 16);
        if (lane < 16) {
            const int r = __brev(lane) >> 28;         // bitrev4 -> accumulator idx
            const int m = 8 * w + (r >> 1);
            g_part2[b][(r & 1) * NMODES + m][pg] = v[0];
        }
    }

    grid_barrier(0);

    // ---------- Phase B+C: reduce partials (per block, smem) + field -----
    // Blocks 0..143: batch b = bb/18, points n0 = (bb%18)*112 .. +111.
    if (bb < 144) {
        const int b  = bb / 18;
        const int n0 = (bb % 18) * NMODES;

        // B: rowsum[r] = sum over 16 particle groups; 2 threads per row.
        {
            const int r = tid >> 1;                   // 0..223
            const int h = tid & 1;
            const float4* p4 = (const float4*)g_part2[b][r];
            float4 u0 = p4[2 * h];
            float4 u1 = p4[2 * h + 1];
            float sum = ((u0.x + u0.y) + (u0.z + u0.w))
                      + ((u1.x + u1.y) + (u1.z + u1.w));
            sum += __shfl_xor_sync(0xffffffffu, sum, 1);
            if (h == 0) rowsum[r] = sum;
        }
        __syncthreads();
        if (tid < NMODES) {
            const int m = tid;
            const double TWO_PI_D = 6.283185307179586476925286766559;
            const double taud  = 12.0 / ((TWO_PI_D * 2001.0) * (TWO_PI_D * 2001.0));
            const float TAUF     = (float)taud;
            const float SQPIOTAU = (float)sqrt(3.14159265358979323846 / taud);
            const float s_   = sigma_var[0];
            const float q0   = 25.f * shift0[0] * shift0[0];
            const float q1   = 25.f * shift1[0] * shift1[0];
            const float FOURPI = 12.566370614359172f;
            const float coef = TAUF - 0.5f * s_ * s_;
            float kk = TWO_PI_F * (float)m;
            float K2 = kk * kk;
            float e  = SQPIOTAU * __expf(coef * K2);  // 0 for m >= 106 (as ref)
            float fold = (m == 0) ? 1.f : 2.f;
            float V0 = fold * (-amp0[0]) * FOURPI / (K2 + q0) * e;
            float inv = 1.f / (K2 + q1);
            float V1 = fold * amp1[0] * FOURPI * inv * inv * e;
            tab4[m] = make_float4(rowsum[m], rowsum[NMODES + m], V0, V1);
        }
        __syncthreads();

        // C: 4 threads per grid point, 28-mode rotation chain each.
        {
            const int q = tid & 3;
            const int n = n0 + (tid >> 2);

            const float C_HI = (float)(1.0 / 2001.0);
            const float C_LO = (float)(1.0 / 2001.0 - (double)((float)(1.0 / 2001.0)));
            const float nf     = (float)n;
            const float phi_hi = nf * C_HI;
            const float phi_lo = fmaf(nf, C_HI, -phi_hi) + nf * C_LO;

            float sw_, cw_;                           // step e^{2*pi*i*phi}
            __sincosf(TWO_PI_F * ((phi_hi - rintf(phi_hi)) + phi_lo), &sw_, &cw_);

            float zr, zi;                             // base at m0 = 28*q (exact)
            if (q == 0) { zr = 1.f; zi = 0.f; }
            else {
                float m0f = (float)(28 * q);
                float hi2 = m0f * phi_hi;
                float lo2 = fmaf(m0f, phi_hi, -hi2);
                float f   = (hi2 - rintf(hi2)) + (lo2 + m0f * phi_lo);
                __sincosf(TWO_PI_F * (f - rintf(f)), &zi, &zr);
            }

            float acc0 = 0.f, acc1 = 0.f;
#pragma unroll
            for (int j = 0; j < 28; ++j) {
                float4 t4 = tab4[28 * q + j];         // LDS, 4-way broadcast
                float tt = fmaf(t4.x, zr, t4.y * zi);
                acc0 = fmaf(t4.z, tt, acc0);
                acc1 = fmaf(t4.w, tt, acc1);
                float nzr = fmaf(zr, cw_, -zi * sw_);
                float nzi = fmaf(zi, cw_,  zr * sw_);
                zr = nzr; zi = nzi;
            }
            acc0 += __shfl_xor_sync(0xffffffffu, acc0, 1);
            acc0 += __shfl_xor_sync(0xffffffffu, acc0, 2);
            acc1 += __shfl_xor_sync(0xffffffffu, acc1, 1);
            acc1 += __shfl_xor_sync(0xffffffffu, acc1, 2);
            if (q == 0 && n < NMESHC) {
                g_f[b][0][n] = acc0;
                g_f[b][1][n] = acc1;
            }
        }
    }

    grid_barrier(1);

    // ---------------- Phase D: resample at particle positions ------------
    {
        const int p = bb * 56 + tid;                  // 148*56 = 8288 >= 8192
        if (tid < 56 && p < NBATCH * NPART) {
            const int b = p >> 10;
            const float xv = x[p];

            const double TWO_PI_D = 6.283185307179586476925286766559;
            const float TAUF    = (float)(12.0 / ((TWO_PI_D * 2001.0) * (TWO_PI_D * 2001.0)));
            const float inv4tau = 1.f / (4.f * TAUF);
            const float C_HI = (float)(1.0 / 2001.0);
            const float C_LO = (float)(1.0 / 2001.0 - (double)((float)(1.0 / 2001.0)));

            const int m0 = __float2int_rn(xv * 2001.0f);
            float acc0 = 0.f, acc1 = 0.f;
#pragma unroll
            for (int j = -7; j <= 7; ++j) {
                int m = m0 + j;
                if (m < 0 || m > 2000) continue;
                float mf = (float)m;
                float hi = mf * C_HI;
                float X  = hi + (fmaf(mf, C_HI, -hi) + mf * C_LO);  // fp32(m/2001)
                float d  = xv - X;
                float wgt = __expf(-d * d * inv4tau);
                acc0 = fmaf(wgt, g_f[b][0][m], acc0);
                acc1 = fmaf(wgt, g_f[b][1][m], acc1);
            }
            const float invN = (float)(1.0 / 2001.0);
            out[2 * p]     = acc0 * invN;
            out[2 * p + 1] = acc1 * invN;
        }
    }
}

// ---------------------------------------------------------------------------
extern "C" void kernel_launch(void* const* d_in, const int* in_sizes, int n_in,
                              void* d_out, int out_size)
{
    (void)in_sizes; (void)n_in; (void)out_size;
    k_fused<<<GRIDB, TPB>>>((const float*)d_in[0], (const float*)d_in[1],
                            (const float*)d_in[2], (const float*)d_in[3],
                            (const float*)d_in[4], (const float*)d_in[5],
                            (float*)d_out);
}

// round 8
// speedup vs baseline: 1.4174x; 1.2430x over previous
#include <cuda_runtime.h>
#include <math.h>

// NUFFT layer — fully analytic. Round-8: ONE grid barrier.
//   Phase A: A[m] = sum_p cos(2*pi*m*x_p), B[m] = sum_p sin(...)  (partials)
//   Phase 2 (per block): reduce partials; then directly
//     out[p,c] = sum_m U_c[m]*(A cos(2*pi*m*x_p) + B sin(2*pi*m*x_p)) - wrap
//   where U_c = fold*M_c*2*pi*exp(-K^2 s^2/2)  (deconv x window transform = 2*pi
//   exactly, by Poisson summation). Wrap corrections (reference CLAMPS the
//   window; Poisson periodizes) subtract (1/N)*w*f(edge grid pt) for the ~30
//   particles within ~6 grid spacings of x=0 or x=1, using a 12-entry edge
//   field table built from the V-table (V = with-deconv multiplier).

#define NMODES 112          // modes >= 106 underflow to exactly 0 (as reference fp32)
#define NBATCH 8
#define NPART  1024
#define BPB    18           // blocks per batch
#define GRIDB  (NBATCH * BPB)   // 144
#define TPB    480

__device__ float    g_part2[NBATCH][2 * NMODES][16];  // [b][A|B x mode][pgroup]
__device__ unsigned g_ctr[1];

#define TWO_PI_F 6.2831853071795864769f

__device__ __forceinline__ float frac_mx(float m, float x)
{   // frac(m*x) in ~[-0.5,0.5]; exact Dekker split (m <= 104 < 2^7, x fp32)
    float hi = m * x;
    float lo = fmaf(m, x, -hi);
    return (hi - rintf(hi)) + lo;
}

__device__ __forceinline__ void grid_barrier()
{
    __syncthreads();
    if (threadIdx.x == 0) {
        __threadfence();
        unsigned v   = atomicAdd(&g_ctr[0], 1u);
        unsigned tgt = v - (v % GRIDB) + GRIDB;   // end of this replay's wave
        unsigned cur;
        do {
            asm volatile("ld.acquire.gpu.u32 %0, [%1];"
                         : "=r"(cur) : "l"(&g_ctr[0]) : "memory");
        } while ((int)(cur - tgt) < 0);
    }
    __syncthreads();
}

__global__ __launch_bounds__(TPB, 1) void k_fused(
    const float* __restrict__ x,
    const float* __restrict__ sigma_var,
    const float* __restrict__ shift0,
    const float* __restrict__ shift1,
    const float* __restrict__ amp0,
    const float* __restrict__ amp1,
    float* __restrict__ out)
{
    const int bb   = blockIdx.x;
    const int tid  = threadIdx.x;
    const int w    = tid >> 5;
    const int lane = tid & 31;

    __shared__ float  rowsum[2 * NMODES];
    __shared__ float4 tabU[NMODES];       // (A, B, U0, U1)  — no-deconv multipliers
    __shared__ float2 tabV[NMODES];       // (V0, V1)        — with-deconv (edge f)
    __shared__ float  sf0[12], sf1[12];   // f at grid pts {0..5, 1995..2000}

    // ---------------- Phase A: per-mode cos/sin partial sums -------------
    // Blocks 0..127: (pg = bb&15, b = bb>>4) own 64 particles; warps 0..13,
    // 8 modes/warp, v[16] accumulators (no spill), 15-shfl halving reduction.
    if (bb < 128 && w < 14) {
        const int pg = bb & 15;
        const int b  = bb >> 4;

        float v[16];
#pragma unroll
        for (int k = 0; k < 16; ++k) v[k] = 0.f;

#pragma unroll
        for (int pp = 0; pp < 2; ++pp) {
            const float xv = x[b * NPART + pg * 64 + pp * 32 + lane];
            float sw_, cw_;                           // step e^{2*pi*i*x}
            __sincosf(TWO_PI_F * (xv - rintf(xv)), &sw_, &cw_);
            float zr, zi;
            if (w == 0) { zr = 1.f; zi = 0.f; }
            else        { __sincosf(TWO_PI_F * frac_mx((float)(8 * w), xv), &zi, &zr); }
#pragma unroll
            for (int j = 0; j < 8; ++j) {
                v[2 * j]     += zr;
                v[2 * j + 1] += zi;
                float nzr = fmaf(zr, cw_, -zi * sw_);
                float nzi = fmaf(zi, cw_,  zr * sw_);
                zr = nzr; zi = nzi;
            }
        }
#pragma unroll
        for (int s = 0; s < 4; ++s) {
            const int  half = 8 >> s;
            const bool up   = (lane >> s) & 1;
#pragma unroll
            for (int k = 0; k < half; ++k) {
                float send = up ? v[k] : v[k + half];
                float recv = __shfl_xor_sync(0xffffffffu, send, 1 << s);
                v[k] = (up ? v[k + half] : v[k]) + recv;
            }
        }
        v[0] += __shfl_xor_sync(0xffffffffu, v[0], 16);
        if (lane < 16) {
            const int r = __brev(lane) >> 28;         // bitrev4 -> accumulator idx
            const int m = 8 * w + (r >> 1);
            g_part2[b][(r & 1) * NMODES + m][pg] = v[0];
        }
    }

    grid_barrier();

    // ================ Phase 2: reduce + direct particle output ===========
    const int b   = bb / BPB;
    const int sub = bb - b * BPB;

    // --- reduce partials: 2 threads per row (224 rows x 16 groups) -------
    if (tid < 448) {
        const int r = tid >> 1;
        const int h = tid & 1;
        const float4* p4 = (const float4*)g_part2[b][r];
        float4 u0 = p4[2 * h];
        float4 u1 = p4[2 * h + 1];
        float sum = ((u0.x + u0.y) + (u0.z + u0.w))
                  + ((u1.x + u1.y) + (u1.z + u1.w));
        sum += __shfl_xor_sync(0xffffffffu, sum, 1);
        if (h == 0) rowsum[r] = sum;
    }
    __syncthreads();

    // --- spectral multiplier tables --------------------------------------
    if (tid < NMODES) {
        const int m = tid;
        const double TWO_PI_D = 6.283185307179586476925286766559;
        const double taud  = 12.0 / ((TWO_PI_D * 2001.0) * (TWO_PI_D * 2001.0));
        const float TAUF     = (float)taud;
        const float SQPIOTAU = (float)sqrt(3.14159265358979323846 / taud);
        const float s_   = sigma_var[0];
        const float q0   = 25.f * shift0[0] * shift0[0];
        const float q1   = 25.f * shift1[0] * shift1[0];
        const float FOURPI = 12.566370614359172f;
        float kk = TWO_PI_F * (float)m;
        float K2 = kk * kk;
        float fold = (m == 0) ? 1.f : 2.f;
        float base0 = fold * (-amp0[0]) * FOURPI / (K2 + q0);
        float inv  = 1.f / (K2 + q1);
        float base1 = fold * amp1[0] * FOURPI * inv * inv;
        float eg = __expf(-0.5f * s_ * s_ * K2);          // 0 for m >= ~106 (as ref)
        float eU = TWO_PI_F * eg;                         // window x deconv = 2*pi
        float eV = SQPIOTAU * __expf((TAUF - 0.5f * s_ * s_) * K2);
        tabU[m] = make_float4(rowsum[m], rowsum[NMODES + m], base0 * eU, base1 * eU);
        tabV[m] = make_float2(base0 * eV, base1 * eV);
    }
    __syncthreads();

    // --- edge field table: f (with deconv) at grid {0..5, 1995..2000} ----
    // Threads 0..63 (warps 0,1 fully): 4 threads/point, 28-mode chains.
    if (tid < 64) {
        const int e = tid >> 2;                       // 0..15 (12 used)
        const int q = tid & 3;
        const int g = (e < 6) ? e : (1995 + (e - 6));

        const float C_HI = (float)(1.0 / 2001.0);
        const float C_LO = (float)(1.0 / 2001.0 - (double)((float)(1.0 / 2001.0)));
        const float gf     = (float)g;
        const float phi_hi = gf * C_HI;
        const float phi_lo = fmaf(gf, C_HI, -phi_hi) + gf * C_LO;

        float sw_, cw_;
        __sincosf(TWO_PI_F * ((phi_hi - rintf(phi_hi)) + phi_lo), &sw_, &cw_);
        float zr, zi;
        if (q == 0) { zr = 1.f; zi = 0.f; }
        else {
            float m0f = (float)(28 * q);
            float hi2 = m0f * phi_hi;
            float lo2 = fmaf(m0f, phi_hi, -hi2);
            float f   = (hi2 - rintf(hi2)) + (lo2 + m0f * phi_lo);
            __sincosf(TWO_PI_F * (f - rintf(f)), &zi, &zr);
        }
        float acc0 = 0.f, acc1 = 0.f;
#pragma unroll
        for (int j = 0; j < 28; ++j) {
            const int m = 28 * q + j;
            float4 t4 = tabU[m];                      // A, B
            float2 v2 = tabV[m];                      // V0, V1
            float tt = fmaf(t4.x, zr, t4.y * zi);
            acc0 = fmaf(v2.x, tt, acc0);
            acc1 = fmaf(v2.y, tt, acc1);
            float nzr = fmaf(zr, cw_, -zi * sw_);
            float nzi = fmaf(zi, cw_,  zr * sw_);
            zr = nzr; zi = nzi;
        }
        acc0 += __shfl_xor_sync(0xffffffffu, acc0, 1);
        acc0 += __shfl_xor_sync(0xffffffffu, acc0, 2);
        acc1 += __shfl_xor_sync(0xffffffffu, acc1, 1);
        acc1 += __shfl_xor_sync(0xffffffffu, acc1, 2);
        if (q == 0 && e < 12) { sf0[e] = acc0; sf1[e] = acc1; }
    }
    __syncthreads();

    // --- main: 8 threads per particle, 14-mode chains --------------------
    {
        const int s  = tid >> 3;                      // 0..59
        const int q  = tid & 7;
        const int pl = sub * 57 + s;
        const bool act = (s < 57) && (pl < NPART);
        const float xv = act ? x[b * NPART + pl] : 0.f;

        float sw_, cw_;                               // step e^{2*pi*i*x}
        __sincosf(TWO_PI_F * (xv - rintf(xv)), &sw_, &cw_);
        float zr, zi;                                 // base at m0 = 14q (exact)
        if (q == 0) { zr = 1.f; zi = 0.f; }
        else        { __sincosf(TWO_PI_F * frac_mx((float)(14 * q), xv), &zi, &zr); }

        float acc0 = 0.f, acc1 = 0.f;
#pragma unroll
        for (int j = 0; j < 14; ++j) {
            float4 t4 = tabU[14 * q + j];
            float tt = fmaf(t4.x, zr, t4.y * zi);
            acc0 = fmaf(t4.z, tt, acc0);
            acc1 = fmaf(t4.w, tt, acc1);
            float nzr = fmaf(zr, cw_, -zi * sw_);
            float nzi = fmaf(zi, cw_,  zr * sw_);
            zr = nzr; zi = nzi;
        }
        acc0 += __shfl_xor_sync(0xffffffffu, acc0, 1);
        acc0 += __shfl_xor_sync(0xffffffffu, acc0, 2);
        acc0 += __shfl_xor_sync(0xffffffffu, acc0, 4);
        acc1 += __shfl_xor_sync(0xffffffffu, acc1, 1);
        acc1 += __shfl_xor_sync(0xffffffffu, acc1, 2);
        acc1 += __shfl_xor_sync(0xffffffffu, acc1, 4);

        if (q == 0 && act) {
            // wrap corrections (reference clamps; Poisson periodizes)
            const double TWO_PI_D = 6.283185307179586476925286766559;
            const float TAUF    = (float)(12.0 / ((TWO_PI_D * 2001.0) * (TWO_PI_D * 2001.0)));
            const float inv4tau = 1.f / (4.f * TAUF);
            const float invN    = (float)(1.0 / 2001.0);
            const int m0 = __float2int_rn(xv * 2001.0f);
            if (m0 <= 6) {
#pragma unroll
                for (int j = 1; j <= 6; ++j) {        // phantom n = -j -> grid 2001-j
                    float d = xv + (float)j * invN;
                    float wgt = invN * __expf(-d * d * inv4tau);
                    acc0 -= wgt * sf0[12 - j];
                    acc1 -= wgt * sf1[12 - j];
                }
            }
            if (m0 >= 1994) {
#pragma unroll
                for (int j = 0; j <= 5; ++j) {        // phantom n = 2001+j -> grid j
                    float d = xv - 1.f - (float)j * invN;
                    float wgt = invN * __expf(-d * d * inv4tau);
                    acc0 -= wgt * sf0[j];
                    acc1 -= wgt * sf1[j];
                }
            }
            const int p = b * NPART + pl;
            out[2 * p]     = acc0;
            out[2 * p + 1] = acc1;
        }
    }
}

// ---------------------------------------------------------------------------
extern "C" void kernel_launch(void* const* d_in, const int* in_sizes, int n_in,
                              void* d_out, int out_size)
{
    (void)in_sizes; (void)n_in; (void)out_size;
    k_fused<<<GRIDB, TPB>>>((const float*)d_in[0], (const float*)d_in[1],
                            (const float*)d_in[2], (const float*)d_in[3],
                            (const float*)d_in[4], (const float*)d_in[5],
                            (float*)d_out);
}